// round 13
// baseline (speedup 1.0000x reference)
#include <cuda_runtime.h>
#include <cuda_bf16.h>
#include <cstdint>

#define USER_NUM 200000
#define ITEM_NUM 100000
#define EMB 64
#define MAX_NE 3200000

// ---------------------------------------------------------------------------
// Scratch (__device__ globals; no allocation allowed)
// ---------------------------------------------------------------------------
__device__ float g_agg[(size_t)USER_NUM * EMB];     // 51.2 MB
__device__ float g_U[(size_t)USER_NUM * EMB];       // 51.2 MB
__device__ int   g_csr_col[MAX_NE];
__device__ float g_csr_val[MAX_NE];
__device__ int   g_cnt[USER_NUM];
__device__ int   g_rs[USER_NUM];
__device__ int   g_cur[USER_NUM];
__device__ int   g_bsum[256];

// ---------------------------------------------------------------------------
// CSR build (identical to the proven R2 path)
// ---------------------------------------------------------------------------
__global__ void zero_int_kernel(int* __restrict__ p, int n) {
    int i = blockIdx.x * blockDim.x + threadIdx.x;
    if (i < n) p[i] = 0;
}

__global__ void hist_kernel(const int* __restrict__ rows, int* __restrict__ cnt, int ne) {
    int i = blockIdx.x * blockDim.x + threadIdx.x;
    if (i < ne) atomicAdd(&cnt[rows[i]], 1);
}

__device__ __forceinline__ int warp_excl_scan(int v, int lane, int* total) {
    int x = v;
    #pragma unroll
    for (int d = 1; d < 32; d <<= 1) {
        int y = __shfl_up_sync(0xffffffffu, x, d);
        if (lane >= d) x += y;
    }
    *total = __shfl_sync(0xffffffffu, x, 31);
    return x - v;
}

__global__ void block_sum_kernel(const int* __restrict__ cnt, int* __restrict__ bsum, int n) {
    __shared__ int wsum[8];
    int tid = threadIdx.x, lane = tid & 31, wid = tid >> 5;
    int base = blockIdx.x * 1024 + tid * 4;
    int s = 0;
    #pragma unroll
    for (int j = 0; j < 4; j++) { int idx = base + j; if (idx < n) s += cnt[idx]; }
    int tot; warp_excl_scan(s, lane, &tot);
    if (lane == 31) wsum[wid] = tot;
    __syncthreads();
    if (tid == 0) {
        int t = 0;
        #pragma unroll
        for (int w = 0; w < 8; w++) t += wsum[w];
        bsum[blockIdx.x] = t;
    }
}

__global__ void scan_bsum_kernel(int* __restrict__ bsum, int nb) {
    __shared__ int wsum[8];
    int tid = threadIdx.x, lane = tid & 31, wid = tid >> 5;
    int v = (tid < nb) ? bsum[tid] : 0;
    int wtot; int ex = warp_excl_scan(v, lane, &wtot);
    if (lane == 31) wsum[wid] = wtot;
    __syncthreads();
    if (wid == 0) {
        int t = (lane < 8) ? wsum[lane] : 0;
        int tt; int e = warp_excl_scan(t, lane, &tt);
        if (lane < 8) wsum[lane] = e;
    }
    __syncthreads();
    if (tid < nb) bsum[tid] = wsum[wid] + ex;
}

__global__ void scan_block_kernel(const int* __restrict__ cnt, const int* __restrict__ boff,
                                  int* __restrict__ rs, int* __restrict__ cur, int n) {
    __shared__ int wsum[8];
    int tid = threadIdx.x, lane = tid & 31, wid = tid >> 5;
    int base = blockIdx.x * 1024 + tid * 4;
    int v[4]; int s = 0;
    #pragma unroll
    for (int j = 0; j < 4; j++) { int idx = base + j; v[j] = (idx < n) ? cnt[idx] : 0; s += v[j]; }
    int wtot; int ex = warp_excl_scan(s, lane, &wtot);
    if (lane == 31) wsum[wid] = wtot;
    __syncthreads();
    if (wid == 0) {
        int t = (lane < 8) ? wsum[lane] : 0;
        int tt; int e = warp_excl_scan(t, lane, &tt);
        if (lane < 8) wsum[lane] = e;
    }
    __syncthreads();
    int off = boff[blockIdx.x] + wsum[wid] + ex;
    #pragma unroll
    for (int j = 0; j < 4; j++) {
        int idx = base + j;
        if (idx < n) { rs[idx] = off; cur[idx] = off; off += v[j]; }
    }
}

__global__ void scatter_kernel(const int* __restrict__ rows, const int* __restrict__ cols,
                               const float* __restrict__ vals, int* __restrict__ cur,
                               int* __restrict__ ccol, float* __restrict__ cval, int ne) {
    int i = blockIdx.x * blockDim.x + threadIdx.x;
    if (i >= ne) return;
    int r = rows[i];
    int p = atomicAdd(&cur[r], 1);
    ccol[p] = cols[i];
    cval[p] = vals[i];
}

// ---------------------------------------------------------------------------
// CSR SpMM (identical to R2)
// ---------------------------------------------------------------------------
__global__ void __launch_bounds__(256)
spmm_csr_kernel(const int* __restrict__ rs, const int* __restrict__ cnt,
                const int* __restrict__ ccol, const float* __restrict__ cval,
                const float4* __restrict__ X4, float4* __restrict__ out4,
                int accumulate) {
    long long t = (long long)blockIdx.x * blockDim.x + threadIdx.x;
    int row = (int)(t >> 4);
    int g   = (int)(t & 15);
    if (row >= USER_NUM) return;
    int s = rs[row];
    int e = s + cnt[row];
    float4 acc;
    if (accumulate) acc = out4[(long long)row * 16 + g];
    else            acc = make_float4(0.f, 0.f, 0.f, 0.f);
    for (int i = s; i < e; i++) {
        int   c = __ldg(&ccol[i]);
        float v = __ldg(&cval[i]);
        float4 x = X4[(long long)c * 16 + g];
        acc.x += v * x.x; acc.y += v * x.y; acc.z += v * x.z; acc.w += v * x.w;
    }
    out4[(long long)row * 16 + g] = acc;
}

// ---------------------------------------------------------------------------
// Tensor-core GEMM + bias + ReLU via mma.sync.m16n8k8.tf32 (3-pass split).
//   out[r,o] = relu( sum_k h[r,k]*W[o,k] + b[o] ),  h = concat(agg, U)
// CTA: 64 rows x 64 outs, 8 warps = 4(M) x 2(N); warp: m16 x n32, K=128.
// Smem holds fragment-PERMUTED tiles (hi/lo tf32 splits) so mainloop frag
// loads are one LDS.128 (A) / LDS.64 (B) per fragment.
// ---------------------------------------------------------------------------
#define NFRAG_FLOATS 8192                 // 16 ksteps * (4|8) groups * 32 * (4|2)
#define SM_AHI 0
#define SM_ALO (NFRAG_FLOATS)
#define SM_BHI (2 * NFRAG_FLOATS)
#define SM_BLO (3 * NFRAG_FLOATS)
#define MMA_SMEM (4 * NFRAG_FLOATS * 4)   // 131072 B

// A fragment permutation: element A[r][k] (r<64, k<128) -> float index
__device__ __forceinline__ int idxA(int r, int k) {
    int wm = r >> 4, rr = r & 15, s = k >> 3, kk = k & 7;
    int l = ((rr & 7) << 2) | (kk & 3);
    int j = ((kk >> 2) << 1) | (rr >> 3);
    return ((s * 4 + wm) * 32 + l) * 4 + j;
}
// B fragment permutation: element W[c][k] (c<64, k<128) -> float index
__device__ __forceinline__ int idxB(int c, int k) {
    int ng = c >> 3, cc = c & 7, s = k >> 3, kk = k & 7;
    int l = (cc << 2) | (kk & 3);
    int j = kk >> 2;
    return ((s * 8 + ng) * 32 + l) * 2 + j;
}

__device__ __forceinline__ void tf32_split(float x, float& hi, float& lo) {
    uint32_t h; asm("cvt.rna.tf32.f32 %0, %1;" : "=r"(h) : "f"(x));
    hi = __uint_as_float(h);
    float r = x - hi;
    uint32_t l; asm("cvt.rna.tf32.f32 %0, %1;" : "=r"(l) : "f"(r));
    lo = __uint_as_float(l);
}

__device__ __forceinline__ void mma_tf32(float4& d, float4 a, float2 b) {
    asm volatile(
        "mma.sync.aligned.m16n8k8.row.col.f32.tf32.tf32.f32 "
        "{%0,%1,%2,%3}, {%4,%5,%6,%7}, {%8,%9}, {%0,%1,%2,%3};"
        : "+f"(d.x), "+f"(d.y), "+f"(d.z), "+f"(d.w)
        : "r"(__float_as_uint(a.x)), "r"(__float_as_uint(a.y)),
          "r"(__float_as_uint(a.z)), "r"(__float_as_uint(a.w)),
          "r"(__float_as_uint(b.x)), "r"(__float_as_uint(b.y)));
}

__global__ void __launch_bounds__(256, 1)
mma_gemm_relu_kernel(const float4* __restrict__ agg4,
                     const float4* __restrict__ u4,
                     const float4* __restrict__ W4,   // [64][32] float4 of [64][128]
                     const float*  __restrict__ bias,
                     float* __restrict__ out) {
    extern __shared__ float sm[];
    int tid = threadIdx.x, lane = tid & 31, wid = tid >> 5;
    long long block_row = (long long)blockIdx.x * 64;

    // ---- stage A = concat(agg, U), tf32 hi/lo, fragment-permuted ----
    #pragma unroll
    for (int i = tid; i < 64 * 32; i += 256) {
        int r = i >> 5, c = i & 31;
        long long grow = block_row + r;
        float4 v = (c < 16) ? agg4[grow * 16 + c] : u4[grow * 16 + (c - 16)];
        float e[4] = {v.x, v.y, v.z, v.w};
        #pragma unroll
        for (int j = 0; j < 4; j++) {
            int k = 4 * c + j;
            float hi, lo; tf32_split(e[j], hi, lo);
            int ix = idxA(r, k);
            sm[SM_AHI + ix] = hi;
            sm[SM_ALO + ix] = lo;
        }
    }
    // ---- stage B = W, tf32 hi/lo, fragment-permuted ----
    #pragma unroll
    for (int i = tid; i < 64 * 32; i += 256) {
        int cc = i >> 5, c4 = i & 31;
        float4 w = W4[cc * 32 + c4];
        float e[4] = {w.x, w.y, w.z, w.w};
        #pragma unroll
        for (int j = 0; j < 4; j++) {
            int k = 4 * c4 + j;
            float hi, lo; tf32_split(e[j], hi, lo);
            int ix = idxB(cc, k);
            sm[SM_BHI + ix] = hi;
            sm[SM_BLO + ix] = lo;
        }
    }
    __syncthreads();

    // ---- mainloop: warp (wm, wn), 3 passes x 16 ksteps x 4 nfrags ----
    int wm = wid & 3, wn = wid >> 2;
    float4 acc[4] = {};

    #pragma unroll 1
    for (int pass = 0; pass < 3; pass++) {
        const float* Ab = sm + ((pass == 1) ? SM_ALO : SM_AHI);
        const float* Bb = sm + ((pass == 2) ? SM_BLO : SM_BHI);
        #pragma unroll 4
        for (int s = 0; s < 16; s++) {
            float4 a = *(const float4*)&Ab[((s * 4 + wm) * 32 + lane) * 4];
            #pragma unroll
            for (int n = 0; n < 4; n++) {
                float2 b = *(const float2*)&Bb[((s * 8 + wn * 4 + n) * 32 + lane) * 2];
                mma_tf32(acc[n], a, b);
            }
        }
    }

    // ---- epilogue: bias + relu, direct gmem stores ----
    long long row0 = block_row + wm * 16 + (lane >> 2);
    #pragma unroll
    for (int n = 0; n < 4; n++) {
        int col = wn * 32 + n * 8 + 2 * (lane & 3);
        float2 bb = *(const float2*)&bias[col];
        float2 lo, hi2;
        lo.x  = fmaxf(acc[n].x + bb.x, 0.f);
        lo.y  = fmaxf(acc[n].y + bb.y, 0.f);
        hi2.x = fmaxf(acc[n].z + bb.x, 0.f);
        hi2.y = fmaxf(acc[n].w + bb.y, 0.f);
        *(float2*)&out[row0 * 64 + col]       = lo;
        *(float2*)&out[(row0 + 8) * 64 + col] = hi2;
    }
}

// ---------------------------------------------------------------------------
// Launch (serial, R2 structure)
// ---------------------------------------------------------------------------
static void build_csr(const int* rows, const int* cols, const float* vals, int ne,
                      int* cnt, int* rs, int* cur, int* bsum, int* ccol, float* cval) {
    const int nb_scan = (USER_NUM + 1023) / 1024;          // 196
    const int eb = (ne + 255) / 256;
    zero_int_kernel<<<(USER_NUM + 255) / 256, 256>>>(cnt, USER_NUM);
    hist_kernel<<<eb, 256>>>(rows, cnt, ne);
    block_sum_kernel<<<nb_scan, 256>>>(cnt, bsum, USER_NUM);
    scan_bsum_kernel<<<1, 256>>>(bsum, nb_scan);
    scan_block_kernel<<<nb_scan, 256>>>(cnt, bsum, rs, cur, USER_NUM);
    scatter_kernel<<<eb, 256>>>(rows, cols, vals, cur, ccol, cval, ne);
}

extern "C" void kernel_launch(void* const* d_in, const int* in_sizes, int n_in,
                              void* d_out, int out_size) {
    const float* user_emb = (const float*)d_in[0];
    const float* item_emb = (const float*)d_in[1];
    const float* W        = (const float*)d_in[2];
    const float* b        = (const float*)d_in[3];
    const int*   s_rows   = (const int*)  d_in[4];
    const int*   s_cols   = (const int*)  d_in[5];
    const float* s_vals   = (const float*)d_in[6];
    const int*   r_rows   = (const int*)  d_in[7];
    const int*   r_cols   = (const int*)  d_in[8];
    const float* r_vals   = (const float*)d_in[9];
    int ne_s = in_sizes[4];
    int ne_r = in_sizes[7];

    float* out_user = (float*)d_out;
    float* out_item = out_user + (size_t)USER_NUM * EMB;

    float *agg, *U1, *cval;
    int *cnt, *rs, *cur, *bsum, *ccol;
    cudaGetSymbolAddress((void**)&agg,  g_agg);
    cudaGetSymbolAddress((void**)&U1,   g_U);
    cudaGetSymbolAddress((void**)&cnt,  g_cnt);
    cudaGetSymbolAddress((void**)&rs,   g_rs);
    cudaGetSymbolAddress((void**)&cur,  g_cur);
    cudaGetSymbolAddress((void**)&bsum, g_bsum);
    cudaGetSymbolAddress((void**)&ccol, g_csr_col);
    cudaGetSymbolAddress((void**)&cval, g_csr_val);

    cudaFuncSetAttribute(mma_gemm_relu_kernel,
                         cudaFuncAttributeMaxDynamicSharedMemorySize, MMA_SMEM);

    const int spmm_gb = (USER_NUM * 16 + 255) / 256;     // 12500
    const int mma_gb  = USER_NUM / 64;                   // 3125

    // ---- CSR(S) build (used by both layers) ----
    build_csr(s_rows, s_cols, s_vals, ne_s, cnt, rs, cur, bsum, ccol, cval);

    // Layer 0
    spmm_csr_kernel<<<spmm_gb, 256>>>(rs, cnt, ccol, cval, (const float4*)user_emb,
                                      (float4*)agg, 0);
    mma_gemm_relu_kernel<<<mma_gb, 256, MMA_SMEM>>>((const float4*)agg, (const float4*)user_emb,
                                                    (const float4*)W, b, U1);
    // Layer 1
    spmm_csr_kernel<<<spmm_gb, 256>>>(rs, cnt, ccol, cval, (const float4*)U1,
                                      (float4*)agg, 0);
    mma_gemm_relu_kernel<<<mma_gb, 256, MMA_SMEM>>>((const float4*)agg, (const float4*)U1,
                                                    (const float4*)(W + 64 * 128), b + 64,
                                                    out_user);

    // ---- CSR(R) build + final accumulate SpMM ----
    build_csr(r_rows, r_cols, r_vals, ne_r, cnt, rs, cur, bsum, ccol, cval);
    spmm_csr_kernel<<<spmm_gb, 256>>>(rs, cnt, ccol, cval, (const float4*)item_emb,
                                      (float4*)out_user, 1);

    // item_all = V
    cudaMemcpyAsync(out_item, item_emb, (size_t)ITEM_NUM * EMB * sizeof(float),
                    cudaMemcpyDeviceToDevice, 0);
}

// round 14
// speedup vs baseline: 1.4791x; 1.4791x over previous
#include <cuda_runtime.h>
#include <cuda_bf16.h>

#define USER_NUM 200000
#define ITEM_NUM 100000
#define EMB 64
#define MAX_NE 3200000

// ---------------------------------------------------------------------------
// Scratch (__device__ globals; no allocation allowed)
// ---------------------------------------------------------------------------
__device__ float g_agg[(size_t)USER_NUM * EMB];     // 51.2 MB
__device__ float g_U[(size_t)USER_NUM * EMB];       // 51.2 MB
// CSR(S)
__device__ int   g_ccolS[MAX_NE];
__device__ float g_cvalS[MAX_NE];
__device__ int   g_cntS[USER_NUM];
__device__ int   g_rsS[USER_NUM];
__device__ int   g_curS[USER_NUM];
__device__ int   g_bsumS[256];
// CSR(R) — separate set: built on a side stream while S is in use
__device__ int   g_ccolR[MAX_NE];
__device__ float g_cvalR[MAX_NE];
__device__ int   g_cntR[USER_NUM];
__device__ int   g_rsR[USER_NUM];
__device__ int   g_curR[USER_NUM];
__device__ int   g_bsumR[256];

// ---------------------------------------------------------------------------
// Side stream + events (created once at load; per-call work is deterministic)
// ---------------------------------------------------------------------------
static cudaStream_t s_side = nullptr;
static cudaEvent_t  s_ev_fork = nullptr, s_ev_join = nullptr;
namespace {
struct SideInit {
    SideInit() {
        cudaStreamCreateWithFlags(&s_side, cudaStreamNonBlocking);
        cudaEventCreateWithFlags(&s_ev_fork, cudaEventDisableTiming);
        cudaEventCreateWithFlags(&s_ev_join, cudaEventDisableTiming);
    }
} s_side_init;
}

// ---------------------------------------------------------------------------
// CSR build kernels (identical to proven R2 path)
// ---------------------------------------------------------------------------
__global__ void zero_int_kernel(int* __restrict__ p, int n) {
    int i = blockIdx.x * blockDim.x + threadIdx.x;
    if (i < n) p[i] = 0;
}

__global__ void hist_kernel(const int* __restrict__ rows, int* __restrict__ cnt, int ne) {
    int i = blockIdx.x * blockDim.x + threadIdx.x;
    if (i < ne) atomicAdd(&cnt[rows[i]], 1);
}

__device__ __forceinline__ int warp_excl_scan(int v, int lane, int* total) {
    int x = v;
    #pragma unroll
    for (int d = 1; d < 32; d <<= 1) {
        int y = __shfl_up_sync(0xffffffffu, x, d);
        if (lane >= d) x += y;
    }
    *total = __shfl_sync(0xffffffffu, x, 31);
    return x - v;
}

__global__ void block_sum_kernel(const int* __restrict__ cnt, int* __restrict__ bsum, int n) {
    __shared__ int wsum[8];
    int tid = threadIdx.x, lane = tid & 31, wid = tid >> 5;
    int base = blockIdx.x * 1024 + tid * 4;
    int s = 0;
    #pragma unroll
    for (int j = 0; j < 4; j++) { int idx = base + j; if (idx < n) s += cnt[idx]; }
    int tot; warp_excl_scan(s, lane, &tot);
    if (lane == 31) wsum[wid] = tot;
    __syncthreads();
    if (tid == 0) {
        int t = 0;
        #pragma unroll
        for (int w = 0; w < 8; w++) t += wsum[w];
        bsum[blockIdx.x] = t;
    }
}

__global__ void scan_bsum_kernel(int* __restrict__ bsum, int nb) {
    __shared__ int wsum[8];
    int tid = threadIdx.x, lane = tid & 31, wid = tid >> 5;
    int v = (tid < nb) ? bsum[tid] : 0;
    int wtot; int ex = warp_excl_scan(v, lane, &wtot);
    if (lane == 31) wsum[wid] = wtot;
    __syncthreads();
    if (wid == 0) {
        int t = (lane < 8) ? wsum[lane] : 0;
        int tt; int e = warp_excl_scan(t, lane, &tt);
        if (lane < 8) wsum[lane] = e;
    }
    __syncthreads();
    if (tid < nb) bsum[tid] = wsum[wid] + ex;
}

__global__ void scan_block_kernel(const int* __restrict__ cnt, const int* __restrict__ boff,
                                  int* __restrict__ rs, int* __restrict__ cur, int n) {
    __shared__ int wsum[8];
    int tid = threadIdx.x, lane = tid & 31, wid = tid >> 5;
    int base = blockIdx.x * 1024 + tid * 4;
    int v[4]; int s = 0;
    #pragma unroll
    for (int j = 0; j < 4; j++) { int idx = base + j; v[j] = (idx < n) ? cnt[idx] : 0; s += v[j]; }
    int wtot; int ex = warp_excl_scan(s, lane, &wtot);
    if (lane == 31) wsum[wid] = wtot;
    __syncthreads();
    if (wid == 0) {
        int t = (lane < 8) ? wsum[lane] : 0;
        int tt; int e = warp_excl_scan(t, lane, &tt);
        if (lane < 8) wsum[lane] = e;
    }
    __syncthreads();
    int off = boff[blockIdx.x] + wsum[wid] + ex;
    #pragma unroll
    for (int j = 0; j < 4; j++) {
        int idx = base + j;
        if (idx < n) { rs[idx] = off; cur[idx] = off; off += v[j]; }
    }
}

__global__ void scatter_kernel(const int* __restrict__ rows, const int* __restrict__ cols,
                               const float* __restrict__ vals, int* __restrict__ cur,
                               int* __restrict__ ccol, float* __restrict__ cval, int ne) {
    int i = blockIdx.x * blockDim.x + threadIdx.x;
    if (i >= ne) return;
    int r = rows[i];
    int p = atomicAdd(&cur[r], 1);
    ccol[p] = cols[i];
    cval[p] = vals[i];
}

// ---------------------------------------------------------------------------
// CSR SpMM (identical to R2): 16 threads/row, register accumulation
// ---------------------------------------------------------------------------
__global__ void __launch_bounds__(256)
spmm_csr_kernel(const int* __restrict__ rs, const int* __restrict__ cnt,
                const int* __restrict__ ccol, const float* __restrict__ cval,
                const float4* __restrict__ X4, float4* __restrict__ out4,
                int accumulate) {
    long long t = (long long)blockIdx.x * blockDim.x + threadIdx.x;
    int row = (int)(t >> 4);
    int g   = (int)(t & 15);
    if (row >= USER_NUM) return;
    int s = rs[row];
    int e = s + cnt[row];
    float4 acc;
    if (accumulate) acc = out4[(long long)row * 16 + g];
    else            acc = make_float4(0.f, 0.f, 0.f, 0.f);
    for (int i = s; i < e; i++) {
        int   c = __ldg(&ccol[i]);
        float v = __ldg(&cval[i]);
        float4 x = X4[(long long)c * 16 + g];
        acc.x += v * x.x; acc.y += v * x.y; acc.z += v * x.z; acc.w += v * x.w;
    }
    out4[(long long)row * 16 + g] = acc;
}

// ---------------------------------------------------------------------------
// Fused GEMM + bias + ReLU (R2 scalar-FFMA version — proven at roofline)
// ---------------------------------------------------------------------------
#define HS_STRIDE 132
#define WS_STRIDE 68
#define GEMM_SMEM ((64 * HS_STRIDE + 128 * WS_STRIDE) * 4)   // 68,608 B

__global__ void __launch_bounds__(256, 3)
gemm_relu_kernel(const float4* __restrict__ agg4,
                 const float4* __restrict__ u4,
                 const float4* __restrict__ W4,   // [64][32] float4 view of [64][128]
                 const float*  __restrict__ bias,
                 float4* __restrict__ out4) {
    extern __shared__ float smem[];
    float* hs = smem;
    float* ws = smem + 64 * HS_STRIDE;

    int tid = threadIdx.x;
    long long block_row = (long long)blockIdx.x * 64;

    #pragma unroll
    for (int i = tid; i < 64 * 32; i += 256) {
        int r = i >> 5, c = i & 31;
        long long grow = block_row + r;
        float4 v = (c < 16) ? agg4[grow * 16 + c] : u4[grow * 16 + (c - 16)];
        *(float4*)&hs[r * HS_STRIDE + c * 4] = v;
    }
    #pragma unroll
    for (int i = tid; i < 64 * 32; i += 256) {
        int o = i & 63, c = i >> 6;
        float4 w = W4[o * 32 + c];
        ws[(4 * c + 0) * WS_STRIDE + o] = w.x;
        ws[(4 * c + 1) * WS_STRIDE + o] = w.y;
        ws[(4 * c + 2) * WS_STRIDE + o] = w.z;
        ws[(4 * c + 3) * WS_STRIDE + o] = w.w;
    }
    __syncthreads();

    int tx = tid & 15, ty = tid >> 4;
    int o0 = tx * 4;
    float acc[4][4] = {};

    #pragma unroll 4
    for (int k4 = 0; k4 < 32; k4++) {
        float4 wv[4];
        #pragma unroll
        for (int j = 0; j < 4; j++)
            wv[j] = *(const float4*)&ws[(4 * k4 + j) * WS_STRIDE + o0];
        #pragma unroll
        for (int ri = 0; ri < 4; ri++) {
            int r = ty * 4 + ri;
            float4 hv = *(const float4*)&hs[r * HS_STRIDE + k4 * 4];
            acc[ri][0] += hv.x * wv[0].x + hv.y * wv[1].x + hv.z * wv[2].x + hv.w * wv[3].x;
            acc[ri][1] += hv.x * wv[0].y + hv.y * wv[1].y + hv.z * wv[2].y + hv.w * wv[3].y;
            acc[ri][2] += hv.x * wv[0].z + hv.y * wv[1].z + hv.z * wv[2].z + hv.w * wv[3].z;
            acc[ri][3] += hv.x * wv[0].w + hv.y * wv[1].w + hv.z * wv[2].w + hv.w * wv[3].w;
        }
    }

    float b0 = bias[o0 + 0], b1 = bias[o0 + 1], b2 = bias[o0 + 2], b3 = bias[o0 + 3];
    #pragma unroll
    for (int ri = 0; ri < 4; ri++) {
        long long r = block_row + ty * 4 + ri;
        float4 v;
        v.x = fmaxf(acc[ri][0] + b0, 0.f);
        v.y = fmaxf(acc[ri][1] + b1, 0.f);
        v.z = fmaxf(acc[ri][2] + b2, 0.f);
        v.w = fmaxf(acc[ri][3] + b3, 0.f);
        out4[r * 16 + tx] = v;
    }
}

// ---------------------------------------------------------------------------
// Launch: serial main path (R2), with the R-build + item copy forked onto a
// side stream AFTER SpMM0 so it overlaps the FMA-bound GEMM window instead of
// the L2-bound SpMM/build window (the R4 mistake).
// ---------------------------------------------------------------------------
static void build_csr(cudaStream_t st,
                      const int* rows, const int* cols, const float* vals, int ne,
                      int* cnt, int* rs, int* cur, int* bsum, int* ccol, float* cval) {
    const int nb_scan = (USER_NUM + 1023) / 1024;          // 196
    const int eb = (ne + 255) / 256;
    zero_int_kernel<<<(USER_NUM + 255) / 256, 256, 0, st>>>(cnt, USER_NUM);
    hist_kernel<<<eb, 256, 0, st>>>(rows, cnt, ne);
    block_sum_kernel<<<nb_scan, 256, 0, st>>>(cnt, bsum, USER_NUM);
    scan_bsum_kernel<<<1, 256, 0, st>>>(bsum, nb_scan);
    scan_block_kernel<<<nb_scan, 256, 0, st>>>(cnt, bsum, rs, cur, USER_NUM);
    scatter_kernel<<<eb, 256, 0, st>>>(rows, cols, vals, cur, ccol, cval, ne);
}

extern "C" void kernel_launch(void* const* d_in, const int* in_sizes, int n_in,
                              void* d_out, int out_size) {
    const float* user_emb = (const float*)d_in[0];
    const float* item_emb = (const float*)d_in[1];
    const float* W        = (const float*)d_in[2];
    const float* b        = (const float*)d_in[3];
    const int*   s_rows   = (const int*)  d_in[4];
    const int*   s_cols   = (const int*)  d_in[5];
    const float* s_vals   = (const float*)d_in[6];
    const int*   r_rows   = (const int*)  d_in[7];
    const int*   r_cols   = (const int*)  d_in[8];
    const float* r_vals   = (const float*)d_in[9];
    int ne_s = in_sizes[4];
    int ne_r = in_sizes[7];

    float* out_user = (float*)d_out;
    float* out_item = out_user + (size_t)USER_NUM * EMB;

    float *agg, *U1, *cvalS, *cvalR;
    int *cntS, *rsS, *curS, *bsumS, *ccolS;
    int *cntR, *rsR, *curR, *bsumR, *ccolR;
    cudaGetSymbolAddress((void**)&agg,   g_agg);
    cudaGetSymbolAddress((void**)&U1,    g_U);
    cudaGetSymbolAddress((void**)&cntS,  g_cntS);
    cudaGetSymbolAddress((void**)&rsS,   g_rsS);
    cudaGetSymbolAddress((void**)&curS,  g_curS);
    cudaGetSymbolAddress((void**)&bsumS, g_bsumS);
    cudaGetSymbolAddress((void**)&ccolS, g_ccolS);
    cudaGetSymbolAddress((void**)&cvalS, g_cvalS);
    cudaGetSymbolAddress((void**)&cntR,  g_cntR);
    cudaGetSymbolAddress((void**)&rsR,   g_rsR);
    cudaGetSymbolAddress((void**)&curR,  g_curR);
    cudaGetSymbolAddress((void**)&bsumR, g_bsumR);
    cudaGetSymbolAddress((void**)&ccolR, g_ccolR);
    cudaGetSymbolAddress((void**)&cvalR, g_cvalR);

    cudaFuncSetAttribute(gemm_relu_kernel,
                         cudaFuncAttributeMaxDynamicSharedMemorySize, GEMM_SMEM);

    const int spmm_gb = (USER_NUM * 16 + 255) / 256;   // 12500
    const int gemm_gb = USER_NUM / 64;                 // 3125
    cudaStream_t s0 = 0;

    // ---- Main path: CSR(S) build + SpMM0 (all L2-bound; keep exclusive) ----
    build_csr(s0, s_rows, s_cols, s_vals, ne_s, cntS, rsS, curS, bsumS, ccolS, cvalS);
    spmm_csr_kernel<<<spmm_gb, 256, 0, s0>>>(rsS, cntS, ccolS, cvalS,
                                             (const float4*)user_emb, (float4*)agg, 0);

    // ---- Fork AFTER SpMM0: R build + item copy overlap the FMA-bound GEMMs ----
    cudaEventRecord(s_ev_fork, s0);
    cudaStreamWaitEvent(s_side, s_ev_fork, 0);
    build_csr(s_side, r_rows, r_cols, r_vals, ne_r, cntR, rsR, curR, bsumR, ccolR, cvalR);
    cudaMemcpyAsync(out_item, item_emb, (size_t)ITEM_NUM * EMB * sizeof(float),
                    cudaMemcpyDeviceToDevice, s_side);
    cudaEventRecord(s_ev_join, s_side);

    // ---- Main path continues: GEMM0, SpMM1, GEMM1 ----
    gemm_relu_kernel<<<gemm_gb, 256, GEMM_SMEM, s0>>>((const float4*)agg,
                                                      (const float4*)user_emb,
                                                      (const float4*)W, b, (float4*)U1);
    spmm_csr_kernel<<<spmm_gb, 256, 0, s0>>>(rsS, cntS, ccolS, cvalS,
                                             (const float4*)U1, (float4*)agg, 0);
    gemm_relu_kernel<<<gemm_gb, 256, GEMM_SMEM, s0>>>((const float4*)agg,
                                                      (const float4*)U1,
                                                      (const float4*)(W + 64 * 128), b + 64,
                                                      (float4*)out_user);

    // ---- Join + final accumulate SpMM: out_user += R @ V ----
    cudaStreamWaitEvent(s0, s_ev_join, 0);
    spmm_csr_kernel<<<spmm_gb, 256, 0, s0>>>(rsR, cntR, ccolR, cvalR,
                                             (const float4*)item_emb,
                                             (float4*)out_user, 1);
}

// round 15
// speedup vs baseline: 1.5497x; 1.0478x over previous
#include <cuda_runtime.h>
#include <cuda_bf16.h>

#define USER_NUM 200000
#define ITEM_NUM 100000
#define EMB 64
#define MAX_NE 3200000
#define NB_SCAN ((USER_NUM + 1023) / 1024)   // 196

// ---------------------------------------------------------------------------
// Scratch (__device__ globals; no allocation allowed)
// ---------------------------------------------------------------------------
__device__ float g_agg[(size_t)USER_NUM * EMB];     // 51.2 MB
__device__ float g_U[(size_t)USER_NUM * EMB];       // 51.2 MB
// CSR(S)
__device__ int   g_ccolS[MAX_NE];
__device__ float g_cvalS[MAX_NE];
__device__ int   g_cntS[USER_NUM];
__device__ int   g_rsS[USER_NUM];
__device__ int   g_curS[USER_NUM];
__device__ int   g_bsumS[256];
// CSR(R)
__device__ int   g_ccolR[MAX_NE];
__device__ float g_cvalR[MAX_NE];
__device__ int   g_cntR[USER_NUM];
__device__ int   g_rsR[USER_NUM];
__device__ int   g_curR[USER_NUM];
__device__ int   g_bsumR[256];

// ---------------------------------------------------------------------------
// Fused dual-matrix CSR build kernels: each launch covers S then R blocks.
// ---------------------------------------------------------------------------
__global__ void zero2_kernel(int* __restrict__ pS, int* __restrict__ pR, int n) {
    int i = blockIdx.x * blockDim.x + threadIdx.x;
    if (i < n)          pS[i] = 0;
    else if (i < 2 * n) pR[i - n] = 0;
}

__global__ void hist2_kernel(const int* __restrict__ rowsS, int* __restrict__ cntS, int neS,
                             const int* __restrict__ rowsR, int* __restrict__ cntR, int neR) {
    int i = blockIdx.x * blockDim.x + threadIdx.x;
    if (i < neS)              atomicAdd(&cntS[rowsS[i]], 1);
    else if (i - neS < neR)   atomicAdd(&cntR[rowsR[i - neS]], 1);
}

__device__ __forceinline__ int warp_excl_scan(int v, int lane, int* total) {
    int x = v;
    #pragma unroll
    for (int d = 1; d < 32; d <<= 1) {
        int y = __shfl_up_sync(0xffffffffu, x, d);
        if (lane >= d) x += y;
    }
    *total = __shfl_sync(0xffffffffu, x, 31);
    return x - v;
}

__global__ void block_sum2_kernel(const int* __restrict__ cntS, int* __restrict__ bsumS,
                                  const int* __restrict__ cntR, int* __restrict__ bsumR,
                                  int n) {
    __shared__ int wsum[8];
    int tid = threadIdx.x, lane = tid & 31, wid = tid >> 5;
    int bb = blockIdx.x;
    const int* cnt  = (bb < NB_SCAN) ? cntS  : cntR;
    int*       bsum = (bb < NB_SCAN) ? bsumS : bsumR;
    int blk = (bb < NB_SCAN) ? bb : bb - NB_SCAN;

    int base = blk * 1024 + tid * 4;
    int s = 0;
    #pragma unroll
    for (int j = 0; j < 4; j++) { int idx = base + j; if (idx < n) s += cnt[idx]; }
    int tot; warp_excl_scan(s, lane, &tot);
    if (lane == 31) wsum[wid] = tot;
    __syncthreads();
    if (tid == 0) {
        int t = 0;
        #pragma unroll
        for (int w = 0; w < 8; w++) t += wsum[w];
        bsum[blk] = t;
    }
}

__global__ void scan_bsum2_kernel(int* __restrict__ bsumS, int* __restrict__ bsumR, int nb) {
    __shared__ int wsum[8];
    int tid = threadIdx.x, lane = tid & 31, wid = tid >> 5;
    int* bsum = (blockIdx.x == 0) ? bsumS : bsumR;
    int v = (tid < nb) ? bsum[tid] : 0;
    int wtot; int ex = warp_excl_scan(v, lane, &wtot);
    if (lane == 31) wsum[wid] = wtot;
    __syncthreads();
    if (wid == 0) {
        int t = (lane < 8) ? wsum[lane] : 0;
        int tt; int e = warp_excl_scan(t, lane, &tt);
        if (lane < 8) wsum[lane] = e;
    }
    __syncthreads();
    if (tid < nb) bsum[tid] = wsum[wid] + ex;
}

__global__ void scan_block2_kernel(const int* __restrict__ cntS, const int* __restrict__ boffS,
                                   int* __restrict__ rsS, int* __restrict__ curS,
                                   const int* __restrict__ cntR, const int* __restrict__ boffR,
                                   int* __restrict__ rsR, int* __restrict__ curR,
                                   int n) {
    __shared__ int wsum[8];
    int tid = threadIdx.x, lane = tid & 31, wid = tid >> 5;
    int bb = blockIdx.x;
    bool isS = (bb < NB_SCAN);
    const int* cnt  = isS ? cntS  : cntR;
    const int* boff = isS ? boffS : boffR;
    int* rs  = isS ? rsS  : rsR;
    int* cur = isS ? curS : curR;
    int blk = isS ? bb : bb - NB_SCAN;

    int base = blk * 1024 + tid * 4;
    int v[4]; int s = 0;
    #pragma unroll
    for (int j = 0; j < 4; j++) { int idx = base + j; v[j] = (idx < n) ? cnt[idx] : 0; s += v[j]; }
    int wtot; int ex = warp_excl_scan(s, lane, &wtot);
    if (lane == 31) wsum[wid] = wtot;
    __syncthreads();
    if (wid == 0) {
        int t = (lane < 8) ? wsum[lane] : 0;
        int tt; int e = warp_excl_scan(t, lane, &tt);
        if (lane < 8) wsum[lane] = e;
    }
    __syncthreads();
    int off = boff[blk] + wsum[wid] + ex;
    #pragma unroll
    for (int j = 0; j < 4; j++) {
        int idx = base + j;
        if (idx < n) { rs[idx] = off; cur[idx] = off; off += v[j]; }
    }
}

__global__ void scatter2_kernel(const int* __restrict__ rowsS, const int* __restrict__ colsS,
                                const float* __restrict__ valsS, int* __restrict__ curS,
                                int* __restrict__ ccolS, float* __restrict__ cvalS, int neS,
                                const int* __restrict__ rowsR, const int* __restrict__ colsR,
                                const float* __restrict__ valsR, int* __restrict__ curR,
                                int* __restrict__ ccolR, float* __restrict__ cvalR, int neR) {
    int i = blockIdx.x * blockDim.x + threadIdx.x;
    if (i < neS) {
        int r = rowsS[i];
        int p = atomicAdd(&curS[r], 1);
        ccolS[p] = colsS[i];
        cvalS[p] = valsS[i];
    } else if (i - neS < neR) {
        int j = i - neS;
        int r = rowsR[j];
        int p = atomicAdd(&curR[r], 1);
        ccolR[p] = colsR[j];
        cvalR[p] = valsR[j];
    }
}

// ---------------------------------------------------------------------------
// CSR SpMM (identical to R2): 16 threads/row, register accumulation
// ---------------------------------------------------------------------------
__global__ void __launch_bounds__(256)
spmm_csr_kernel(const int* __restrict__ rs, const int* __restrict__ cnt,
                const int* __restrict__ ccol, const float* __restrict__ cval,
                const float4* __restrict__ X4, float4* __restrict__ out4,
                int accumulate) {
    long long t = (long long)blockIdx.x * blockDim.x + threadIdx.x;
    int row = (int)(t >> 4);
    int g   = (int)(t & 15);
    if (row >= USER_NUM) return;
    int s = rs[row];
    int e = s + cnt[row];
    float4 acc;
    if (accumulate) acc = out4[(long long)row * 16 + g];
    else            acc = make_float4(0.f, 0.f, 0.f, 0.f);
    for (int i = s; i < e; i++) {
        int   c = __ldg(&ccol[i]);
        float v = __ldg(&cval[i]);
        float4 x = X4[(long long)c * 16 + g];
        acc.x += v * x.x; acc.y += v * x.y; acc.z += v * x.z; acc.w += v * x.w;
    }
    out4[(long long)row * 16 + g] = acc;
}

// ---------------------------------------------------------------------------
// Fused GEMM + bias + ReLU (R2 scalar-FFMA version — proven at roofline)
// ---------------------------------------------------------------------------
#define HS_STRIDE 132
#define WS_STRIDE 68
#define GEMM_SMEM ((64 * HS_STRIDE + 128 * WS_STRIDE) * 4)   // 68,608 B

__global__ void __launch_bounds__(256, 3)
gemm_relu_kernel(const float4* __restrict__ agg4,
                 const float4* __restrict__ u4,
                 const float4* __restrict__ W4,   // [64][32] float4 view of [64][128]
                 const float*  __restrict__ bias,
                 float4* __restrict__ out4) {
    extern __shared__ float smem[];
    float* hs = smem;
    float* ws = smem + 64 * HS_STRIDE;

    int tid = threadIdx.x;
    long long block_row = (long long)blockIdx.x * 64;

    #pragma unroll
    for (int i = tid; i < 64 * 32; i += 256) {
        int r = i >> 5, c = i & 31;
        long long grow = block_row + r;
        float4 v = (c < 16) ? agg4[grow * 16 + c] : u4[grow * 16 + (c - 16)];
        *(float4*)&hs[r * HS_STRIDE + c * 4] = v;
    }
    #pragma unroll
    for (int i = tid; i < 64 * 32; i += 256) {
        int o = i & 63, c = i >> 6;
        float4 w = W4[o * 32 + c];
        ws[(4 * c + 0) * WS_STRIDE + o] = w.x;
        ws[(4 * c + 1) * WS_STRIDE + o] = w.y;
        ws[(4 * c + 2) * WS_STRIDE + o] = w.z;
        ws[(4 * c + 3) * WS_STRIDE + o] = w.w;
    }
    __syncthreads();

    int tx = tid & 15, ty = tid >> 4;
    int o0 = tx * 4;
    float acc[4][4] = {};

    #pragma unroll 4
    for (int k4 = 0; k4 < 32; k4++) {
        float4 wv[4];
        #pragma unroll
        for (int j = 0; j < 4; j++)
            wv[j] = *(const float4*)&ws[(4 * k4 + j) * WS_STRIDE + o0];
        #pragma unroll
        for (int ri = 0; ri < 4; ri++) {
            int r = ty * 4 + ri;
            float4 hv = *(const float4*)&hs[r * HS_STRIDE + k4 * 4];
            acc[ri][0] += hv.x * wv[0].x + hv.y * wv[1].x + hv.z * wv[2].x + hv.w * wv[3].x;
            acc[ri][1] += hv.x * wv[0].y + hv.y * wv[1].y + hv.z * wv[2].y + hv.w * wv[3].y;
            acc[ri][2] += hv.x * wv[0].z + hv.y * wv[1].z + hv.z * wv[2].z + hv.w * wv[3].z;
            acc[ri][3] += hv.x * wv[0].w + hv.y * wv[1].w + hv.z * wv[2].w + hv.w * wv[3].w;
        }
    }

    float b0 = bias[o0 + 0], b1 = bias[o0 + 1], b2 = bias[o0 + 2], b3 = bias[o0 + 3];
    #pragma unroll
    for (int ri = 0; ri < 4; ri++) {
        long long r = block_row + ty * 4 + ri;
        float4 v;
        v.x = fmaxf(acc[ri][0] + b0, 0.f);
        v.y = fmaxf(acc[ri][1] + b1, 0.f);
        v.z = fmaxf(acc[ri][2] + b2, 0.f);
        v.w = fmaxf(acc[ri][3] + b3, 0.f);
        out4[r * 16 + tx] = v;
    }
}

// ---------------------------------------------------------------------------
// Launch: fully serial on stream 0; both CSR builds fused per-launch.
// ---------------------------------------------------------------------------
extern "C" void kernel_launch(void* const* d_in, const int* in_sizes, int n_in,
                              void* d_out, int out_size) {
    const float* user_emb = (const float*)d_in[0];
    const float* item_emb = (const float*)d_in[1];
    const float* W        = (const float*)d_in[2];
    const float* b        = (const float*)d_in[3];
    const int*   s_rows   = (const int*)  d_in[4];
    const int*   s_cols   = (const int*)  d_in[5];
    const float* s_vals   = (const float*)d_in[6];
    const int*   r_rows   = (const int*)  d_in[7];
    const int*   r_cols   = (const int*)  d_in[8];
    const float* r_vals   = (const float*)d_in[9];
    int ne_s = in_sizes[4];
    int ne_r = in_sizes[7];

    float* out_user = (float*)d_out;
    float* out_item = out_user + (size_t)USER_NUM * EMB;

    float *agg, *U1, *cvalS, *cvalR;
    int *cntS, *rsS, *curS, *bsumS, *ccolS;
    int *cntR, *rsR, *curR, *bsumR, *ccolR;
    cudaGetSymbolAddress((void**)&agg,   g_agg);
    cudaGetSymbolAddress((void**)&U1,    g_U);
    cudaGetSymbolAddress((void**)&cntS,  g_cntS);
    cudaGetSymbolAddress((void**)&rsS,   g_rsS);
    cudaGetSymbolAddress((void**)&curS,  g_curS);
    cudaGetSymbolAddress((void**)&bsumS, g_bsumS);
    cudaGetSymbolAddress((void**)&ccolS, g_ccolS);
    cudaGetSymbolAddress((void**)&cvalS, g_cvalS);
    cudaGetSymbolAddress((void**)&cntR,  g_cntR);
    cudaGetSymbolAddress((void**)&rsR,   g_rsR);
    cudaGetSymbolAddress((void**)&curR,  g_curR);
    cudaGetSymbolAddress((void**)&bsumR, g_bsumR);
    cudaGetSymbolAddress((void**)&ccolR, g_ccolR);
    cudaGetSymbolAddress((void**)&cvalR, g_cvalR);

    cudaFuncSetAttribute(gemm_relu_kernel,
                         cudaFuncAttributeMaxDynamicSharedMemorySize, GEMM_SMEM);

    const int spmm_gb = (USER_NUM * 16 + 255) / 256;            // 12500
    const int gemm_gb = USER_NUM / 64;                          // 3125
    const int zb2     = (2 * USER_NUM + 255) / 256;
    const int hb2     = (ne_s + ne_r + 255) / 256;

    // item_all = V (independent; front-load before heavy L2 phases)
    cudaMemcpyAsync(out_item, item_emb, (size_t)ITEM_NUM * EMB * sizeof(float),
                    cudaMemcpyDeviceToDevice, 0);

    // ---- Fused CSR build for S and R (6 launches total) ----
    zero2_kernel<<<zb2, 256>>>(cntS, cntR, USER_NUM);
    hist2_kernel<<<hb2, 256>>>(s_rows, cntS, ne_s, r_rows, cntR, ne_r);
    block_sum2_kernel<<<2 * NB_SCAN, 256>>>(cntS, bsumS, cntR, bsumR, USER_NUM);
    scan_bsum2_kernel<<<2, 256>>>(bsumS, bsumR, NB_SCAN);
    scan_block2_kernel<<<2 * NB_SCAN, 256>>>(cntS, bsumS, rsS, curS,
                                             cntR, bsumR, rsR, curR, USER_NUM);
    scatter2_kernel<<<hb2, 256>>>(s_rows, s_cols, s_vals, curS, ccolS, cvalS, ne_s,
                                  r_rows, r_cols, r_vals, curR, ccolR, cvalR, ne_r);

    // ---- Layer 0 ----
    spmm_csr_kernel<<<spmm_gb, 256>>>(rsS, cntS, ccolS, cvalS,
                                      (const float4*)user_emb, (float4*)agg, 0);
    gemm_relu_kernel<<<gemm_gb, 256, GEMM_SMEM>>>((const float4*)agg,
                                                  (const float4*)user_emb,
                                                  (const float4*)W, b, (float4*)U1);
    // ---- Layer 1 ----
    spmm_csr_kernel<<<spmm_gb, 256>>>(rsS, cntS, ccolS, cvalS,
                                      (const float4*)U1, (float4*)agg, 0);
    gemm_relu_kernel<<<gemm_gb, 256, GEMM_SMEM>>>((const float4*)agg,
                                                  (const float4*)U1,
                                                  (const float4*)(W + 64 * 128), b + 64,
                                                  (float4*)out_user);

    // ---- Final accumulate: out_user += R @ V ----
    spmm_csr_kernel<<<spmm_gb, 256>>>(rsR, cntR, ccolR, cvalR,
                                      (const float4*)item_emb, (float4*)out_user, 1);
}